// round 5
// baseline (speedup 1.0000x reference)
#include <cuda_runtime.h>
#include <cuda_fp16.h>
#include <cstdint>

// ---------------------------------------------------------------------------
// y = sum_b ((x*v2_b) @ sign(V_b)^T * (v1_b*u2_b)) @ sign(U_b)^T * u1_b + bias
// M=8192, IN=4096, SPLIT=1024, OUT=4096, 2 branches.
// Prep fp16 operands (signs exact, u1 folded into Wu, v2 into x), then two
// mma.sync (HMMA.16816) GEMMs: G1 per branch -> Hcat[8192,2048] fp16 scaled
// by s1; G2 (K=2048) -> fp32 out + bias. tcgen05 unavailable: harness PTX
// target is plain compute_103.
// ---------------------------------------------------------------------------

#define BM 128
#define BN 128
#define BK 32
#define STG 4
#define ROWB 80                 // padded row stride in bytes (40 halfs)
#define TILEB (BM*ROWB)         // 10240
#define STGB (2*TILEB)          // 20480
#define SMEMB (STG*STGB)        // 81920

__device__ __align__(16) __half g_xs[2ull*8192*4096];
__device__ __align__(16) __half g_wv[2ull*1024*4096];
__device__ __align__(16) __half g_wu[4096ull*2048];
__device__ __align__(16) __half g_h [8192ull*2048];
__device__ float g_s1[2048];

__device__ __forceinline__ uint32_t smem_u32(const void* p){
  uint32_t a;
  asm("{ .reg .u64 t; cvta.to.shared.u64 t, %1; cvt.u32.u64 %0, t; }" : "=r"(a) : "l"(p));
  return a;
}
__device__ __forceinline__ void cp16(uint32_t dst, const void* src){
  asm volatile("cp.async.cg.shared.global [%0], [%1], 16;" :: "r"(dst), "l"(src));
}
__device__ __forceinline__ void ldsm4(uint32_t& r0, uint32_t& r1, uint32_t& r2,
                                      uint32_t& r3, uint32_t addr){
  asm volatile("ldmatrix.sync.aligned.m8n8.x4.shared.b16 {%0,%1,%2,%3}, [%4];"
    : "=r"(r0), "=r"(r1), "=r"(r2), "=r"(r3) : "r"(addr));
}
__device__ __forceinline__ void mma16816(float* d, const uint32_t* a, const uint32_t* b){
  asm volatile("mma.sync.aligned.m16n8k16.row.col.f32.f16.f16.f32 "
    "{%0,%1,%2,%3}, {%4,%5,%6,%7}, {%8,%9}, {%0,%1,%2,%3};"
    : "+f"(d[0]), "+f"(d[1]), "+f"(d[2]), "+f"(d[3])
    : "r"(a[0]), "r"(a[1]), "r"(a[2]), "r"(a[3]), "r"(b[0]), "r"(b[1]));
}
__device__ __forceinline__ float sg(float v){ return v > 0.f ? 1.f : (v < 0.f ? -1.f : 0.f); }
__device__ __forceinline__ uint2 pack4(float a, float b, float c, float d){
  __half2 h0 = __floats2half2_rn(a, b), h1 = __floats2half2_rn(c, d);
  uint2 o;
  o.x = *reinterpret_cast<uint32_t*>(&h0);
  o.y = *reinterpret_cast<uint32_t*>(&h1);
  return o;
}

// ------------------------------- prep kernels -------------------------------
__global__ void prep_x_k(const float4* __restrict__ x, const float* __restrict__ v2,
                         const float* __restrict__ v2R){
  uint2* oA = reinterpret_cast<uint2*>(g_xs);
  uint2* oB = reinterpret_cast<uint2*>(g_xs + 8192ull*4096);
  const size_t n = 8388608ull; // 8192*4096/4
  for (size_t i = blockIdx.x*(size_t)blockDim.x + threadIdx.x; i < n;
       i += (size_t)gridDim.x*blockDim.x){
    float4 xv = x[i];
    int k = (int)(i & 1023) * 4;
    float4 a = *(const float4*)(v2 + k);
    float4 b = *(const float4*)(v2R + k);
    oA[i] = pack4(xv.x*a.x, xv.y*a.y, xv.z*a.z, xv.w*a.w);
    oB[i] = pack4(xv.x*b.x, xv.y*b.y, xv.z*b.z, xv.w*b.w);
  }
}

__global__ void prep_wv_k(const float4* __restrict__ V, const float4* __restrict__ VR){
  uint2* oA = reinterpret_cast<uint2*>(g_wv);
  uint2* oB = reinterpret_cast<uint2*>(g_wv + 1024ull*4096);
  const size_t n = 1048576ull; // 1024*4096/4
  for (size_t i = blockIdx.x*(size_t)blockDim.x + threadIdx.x; i < n;
       i += (size_t)gridDim.x*blockDim.x){
    float4 v = V[i];
    oA[i] = pack4(sg(v.x), sg(v.y), sg(v.z), sg(v.w));
    float4 r = VR[i];
    oB[i] = pack4(sg(r.x), sg(r.y), sg(r.z), sg(r.w));
  }
}

__global__ void prep_wu_k(const float4* __restrict__ U, const float4* __restrict__ UR,
                          const float* __restrict__ u1, const float* __restrict__ u1R){
  uint2* o = reinterpret_cast<uint2*>(g_wu);
  const size_t n = 1048576ull; // 4096*1024/4
  for (size_t i = blockIdx.x*(size_t)blockDim.x + threadIdx.x; i < n;
       i += (size_t)gridDim.x*blockDim.x){
    int orow = (int)(i >> 8), j4 = (int)(i & 255);
    float s  = u1[orow], sR = u1R[orow];
    float4 u = U[i];
    o[(size_t)orow*512 + j4]       = pack4(sg(u.x)*s,  sg(u.y)*s,  sg(u.z)*s,  sg(u.w)*s);
    float4 r = UR[i];
    o[(size_t)orow*512 + 256 + j4] = pack4(sg(r.x)*sR, sg(r.y)*sR, sg(r.z)*sR, sg(r.w)*sR);
  }
}

__global__ void prep_s1_k(const float* v1, const float* u2,
                          const float* v1R, const float* u2R){
  int j = blockIdx.x*blockDim.x + threadIdx.x;
  if (j < 1024){ g_s1[j] = v1[j]*u2[j]; g_s1[1024+j] = v1R[j]*u2R[j]; }
}

// -------------------------------- GEMM --------------------------------------
// D[M,N] = A[M,K] @ B[N,K]^T, fp16 in, fp32 accum, 256 thr, 8 warps (2x4),
// warp tile 64x32, 4-stage cp.async ring, 80B-padded smem rows (conflict-free
// ldmatrix: row stride 20 words -> 8 rows cover all 32 banks exactly once).
// MODE 0: outH[row*2048 + bz*1024 + col] = half(acc * aux[bz*1024+col])
// MODE 1: outF[row*4096 + col] = acc + aux[col]
template<int MODE>
__global__ void __launch_bounds__(256)
gemm_k(const __half* __restrict__ A, const __half* __restrict__ B, int K,
       size_t strideA, size_t strideB, const float* __restrict__ aux,
       __half* __restrict__ outH, float* __restrict__ outF)
{
  extern __shared__ char smem[];
  const uint32_t sb = smem_u32(smem);
  const int tid = threadIdx.x, wid = tid >> 5, lane = tid & 31;
  const int bx = blockIdx.x, by = blockIdx.y, bz = blockIdx.z;
  const int wrow = wid >> 2, wcol = wid & 3;

  const __half* Ab = A + strideA*bz + (size_t)bx*BM*K;
  const __half* Bb = B + strideB*bz + (size_t)by*BN*K;
  const int KS = K / BK;

  // two A-chunks + two B-chunks per thread per stage (chunk = 16B)
  const int r0c = tid >> 2,        ch0 = (tid & 3);
  const int r1c = (tid + 256) >> 2, ch1 = ch0;  // c1 = tid+256 -> same ch, r+64

  #define LOAD_STAGE(buf, ks_) do {                                          \
    uint32_t as_ = sb + (buf)*STGB, bs_ = as_ + TILEB;                       \
    int k0_ = (ks_)*BK;                                                      \
    cp16(as_ + r0c*ROWB + ch0*16, Ab + (size_t)r0c*K + k0_ + ch0*8);         \
    cp16(bs_ + r0c*ROWB + ch0*16, Bb + (size_t)r0c*K + k0_ + ch0*8);         \
    cp16(as_ + r1c*ROWB + ch1*16, Ab + (size_t)r1c*K + k0_ + ch1*8);         \
    cp16(bs_ + r1c*ROWB + ch1*16, Bb + (size_t)r1c*K + k0_ + ch1*8);         \
    asm volatile("cp.async.commit_group;" ::: "memory");                     \
  } while(0)

  LOAD_STAGE(0, 0);
  LOAD_STAGE(1, 1);
  LOAD_STAGE(2, 2);

  float acc[4][4][4];
  #pragma unroll
  for (int i = 0; i < 4; i++)
    #pragma unroll
    for (int j = 0; j < 4; j++)
      #pragma unroll
      for (int k = 0; k < 4; k++) acc[i][j][k] = 0.f;

  // per-lane ldmatrix base offsets (lane&15 = row within 16, lane>>4 = 8-col half)
  const uint32_t aBase = (uint32_t)((wrow*64 + (lane & 15))*ROWB + (lane >> 4)*16);
  const uint32_t bBase = (uint32_t)((wcol*32 + (lane & 15))*ROWB + (lane >> 4)*16);

  for (int ks = 0; ks < KS; ks++){
    asm volatile("cp.async.wait_group %0;" :: "n"(STG-2) : "memory");
    __syncthreads();
    if (ks + STG - 1 < KS){
      LOAD_STAGE((ks + STG - 1) & (STG - 1), ks + STG - 1);
    } else {
      asm volatile("cp.async.commit_group;" ::: "memory");  // keep accounting uniform
    }

    const uint32_t as = sb + (ks & (STG-1))*STGB;
    const uint32_t bs = as + TILEB;

    uint32_t ar[4][2][4], br[4][2][2];
    #pragma unroll
    for (int kf = 0; kf < 2; kf++){
      #pragma unroll
      for (int mf = 0; mf < 4; mf++)
        ldsm4(ar[mf][kf][0], ar[mf][kf][1], ar[mf][kf][2], ar[mf][kf][3],
              as + aBase + mf*(16*ROWB) + kf*32);
      #pragma unroll
      for (int nf2 = 0; nf2 < 2; nf2++){
        uint32_t t0, t1, t2, t3;
        ldsm4(t0, t1, t2, t3, bs + bBase + nf2*(16*ROWB) + kf*32);
        br[nf2*2+0][kf][0] = t0; br[nf2*2+1][kf][0] = t1;
        br[nf2*2+0][kf][1] = t2; br[nf2*2+1][kf][1] = t3;
      }
    }
    #pragma unroll
    for (int kf = 0; kf < 2; kf++)
      #pragma unroll
      for (int mf = 0; mf < 4; mf++)
        #pragma unroll
        for (int nf = 0; nf < 4; nf++)
          mma16816(acc[mf][nf], ar[mf][kf], br[nf][kf]);
  }

  // ----------------------------- epilogue -----------------------------------
  const int row0 = bx*BM + wrow*64 + (lane >> 2);
  const int col0 = by*BN + wcol*32 + (lane & 3)*2;

  if (MODE == 0){
    #pragma unroll
    for (int mf = 0; mf < 4; mf++)
      #pragma unroll
      for (int nf = 0; nf < 4; nf++){
        size_t gc = (size_t)bz*1024 + col0 + nf*8;
        float2 s = *(const float2*)(aux + gc);
        int r = row0 + mf*16;
        __half2 lo = __floats2half2_rn(acc[mf][nf][0]*s.x, acc[mf][nf][1]*s.y);
        __half2 hi = __floats2half2_rn(acc[mf][nf][2]*s.x, acc[mf][nf][3]*s.y);
        *reinterpret_cast<__half2*>(outH + (size_t)r*2048 + gc) = lo;
        *reinterpret_cast<__half2*>(outH + (size_t)(r+8)*2048 + gc) = hi;
      }
  } else {
    #pragma unroll
    for (int mf = 0; mf < 4; mf++)
      #pragma unroll
      for (int nf = 0; nf < 4; nf++){
        int c = col0 + nf*8;
        float2 b2 = *(const float2*)(aux + c);
        int r = row0 + mf*16;
        float2 lo = make_float2(acc[mf][nf][0] + b2.x, acc[mf][nf][1] + b2.y);
        float2 hi = make_float2(acc[mf][nf][2] + b2.x, acc[mf][nf][3] + b2.y);
        *reinterpret_cast<float2*>(outF + (size_t)r*4096 + c) = lo;
        *reinterpret_cast<float2*>(outF + (size_t)(r+8)*4096 + c) = hi;
      }
  }
  #undef LOAD_STAGE
}

// ----------------------------- launch ---------------------------------------
extern "C" void kernel_launch(void* const* d_in, const int* in_sizes, int n_in,
                              void* d_out, int out_size){
  (void)in_sizes; (void)n_in; (void)out_size;
  const float* x    = (const float*)d_in[0];
  const float* V    = (const float*)d_in[1];
  const float* U    = (const float*)d_in[2];
  const float* v2   = (const float*)d_in[3];
  const float* v1   = (const float*)d_in[4];
  const float* u2   = (const float*)d_in[5];
  const float* u1   = (const float*)d_in[6];
  const float* V_R  = (const float*)d_in[7];
  const float* U_R  = (const float*)d_in[8];
  const float* v2_R = (const float*)d_in[9];
  const float* v1_R = (const float*)d_in[10];
  const float* u2_R = (const float*)d_in[11];
  const float* u1_R = (const float*)d_in[12];
  const float* bias = (const float*)d_in[13];
  float* out = (float*)d_out;

  __half *xs, *wv, *wu, *h; float* s1;
  cudaGetSymbolAddress((void**)&xs, g_xs);
  cudaGetSymbolAddress((void**)&wv, g_wv);
  cudaGetSymbolAddress((void**)&wu, g_wu);
  cudaGetSymbolAddress((void**)&h,  g_h);
  cudaGetSymbolAddress((void**)&s1, g_s1);

  prep_x_k <<<4096, 256>>>((const float4*)x, v2, v2_R);
  prep_wv_k<<<1024, 256>>>((const float4*)V, (const float4*)V_R);
  prep_wu_k<<<1024, 256>>>((const float4*)U, (const float4*)U_R, u1, u1_R);
  prep_s1_k<<<4, 256>>>(v1, u2, v1_R, u2_R);

  cudaFuncSetAttribute(gemm_k<0>, cudaFuncAttributeMaxDynamicSharedMemorySize, SMEMB);
  cudaFuncSetAttribute(gemm_k<1>, cudaFuncAttributeMaxDynamicSharedMemorySize, SMEMB);

  dim3 g1(64, 8, 2);   // M-tiles x N-tiles(1024/128) x branch
  gemm_k<0><<<g1, 256, SMEMB>>>(xs, wv, 4096, 8192ull*4096, 1024ull*4096,
                                s1, h, nullptr);
  dim3 g2(64, 32, 1);  // M-tiles x N-tiles(4096/128)
  gemm_k<1><<<g2, 256, SMEMB>>>(h, wu, 2048, 0, 0, bias, nullptr, out);
}